// round 14
// baseline (speedup 1.0000x reference)
#include <cuda_runtime.h>
#include <cstdint>

#define BB 16
#define NN 2048
#define DD 64
#define SCn 67
#define SCP 96
#define COVP 80
#define NP 512
#define NS 32
#define GCOLSP 2304
#define XYZCOL 2112
#define GXCOL 2116
#define ECV 96          // conv0 varying channels padded (67 -> 96)
#define CONV_N 16384

#define OFF_L 0
#define OFF_0 1024
#define OFF_1 1280
#define OFF_2 1536

__device__ float d_xyz_t[BB*NN*3];
__device__ float d_xn[BB*NN];
__device__ float d_pts[BB*NN*DD];
__device__ int   d_idx[BB*NN*NS];
__device__ float d_agg[(long)BB*SCP*NN];
__device__ float d_h2[BB*NP*NN];
__device__ float d_norm[BB*NP];
__device__ int   d_amax[NP];
__device__ float d_scale1[SCn];
__device__ float d_scale2[NP],  d_shift2[NP];
__device__ float d_scaleC0[128], d_shiftC0[128];
__device__ float d_scaleC1[128], d_shiftC1[128];
__device__ float d_scaleC2[256], d_shiftC2[256];
__device__ float d_inner[BB*NP*NP];
__device__ float d_bmat[(long)BB*NN*GCOLSP];
__device__ float d_sg[BB*NP*GCOLSP];
__device__ float d_edge[(long)BB*ECV*CONV_N];
__device__ float d_spmat[BB*ECV*NP];
__device__ float d_yinv[(long)BB*128*NP];
__device__ float d_y1[(long)BB*128*CONV_N];
__device__ float d_y2[(long)BB*128*CONV_N];
__device__ float d_ymax[(long)BB*256*NP];
__device__ float d_ymin[(long)BB*256*NP];
__device__ float d_w2p[NP*SCP];
__device__ float d_w0var[128*ECV];
__device__ float d_w0inv[128*ECV];
__device__ float d_w1r[128*128];
__device__ float d_w2r[256*128];
__device__ float d_cov[COVP*COVP];
__device__ float d_mu[COVP];
__device__ float d_stats[2048];
__device__ float d_bsum[BB];
__device__ int   d_unique;

__device__ __forceinline__ uint32_t tf32b(float x) {
    uint32_t u; asm("cvt.rna.tf32.f32 %0, %1;" : "=r"(u) : "f"(x)); return u;
}
__device__ __forceinline__ float tfr(float x) { return __uint_as_float(tf32b(x)); }

__device__ __forceinline__ void ldsm4(uint32_t& r0, uint32_t& r1, uint32_t& r2, uint32_t& r3, uint32_t addr) {
    asm volatile("ldmatrix.sync.aligned.m8n8.x4.shared.b16 {%0,%1,%2,%3}, [%4];"
        : "=r"(r0), "=r"(r1), "=r"(r2), "=r"(r3) : "r"(addr));
}
__device__ __forceinline__ void ldsm2(uint32_t& r0, uint32_t& r1, uint32_t addr) {
    asm volatile("ldmatrix.sync.aligned.m8n8.x2.shared.b16 {%0,%1}, [%2];"
        : "=r"(r0), "=r"(r1) : "r"(addr));
}

// ---------------- prep: xyz transpose + norms + zero accumulators ----------
__global__ void k_prepxyz(const float* __restrict__ xyz) {
    int i = blockIdx.x * blockDim.x + threadIdx.x;
    if (i < 2048) d_stats[i] = 0.f;
    if (i < COVP*COVP) d_cov[i] = 0.f;
    if (i < COVP) d_mu[i] = 0.f;
    if (i >= BB*NN) return;
    int b = i / NN, n = i % NN;
    float x = xyz[(b*3+0)*NN + n];
    float y = xyz[(b*3+1)*NN + n];
    float z = xyz[(b*3+2)*NN + n];
    d_xyz_t[i*3+0] = x; d_xyz_t[i*3+1] = y; d_xyz_t[i*3+2] = z;
    d_xn[i] = x*x + y*y + z*z;
}

// ---------------- pts tiled transpose ----------------
__global__ void k_transp(const float* __restrict__ pts) {
    __shared__ float tile[32][33];
    int n0 = blockIdx.x * 32, c0 = blockIdx.y * 32, b = blockIdx.z;
    int tx = threadIdx.x, ty = threadIdx.y;
    #pragma unroll
    for (int r = 0; r < 4; r++)
        tile[ty + 8*r][tx] = pts[((long)b*DD + c0 + ty + 8*r)*NN + n0 + tx];
    __syncthreads();
    #pragma unroll
    for (int r = 0; r < 4; r++)
        d_pts[((long)b*NN + n0 + ty + 8*r)*DD + c0 + tx] = tile[tx][ty + 8*r];
}

// ---------------- agg ----------------
__global__ void k_agg(const float* __restrict__ xyz, const float* __restrict__ pts) {
    long i = (long)blockIdx.x*blockDim.x + threadIdx.x;
    long tot4 = (long)BB*SCP*NN/4;
    if (i >= tot4) return;
    long e = i*4;
    int n = (int)(e % NN); long bc = e / NN; int c = (int)(bc % SCP); int b = (int)(bc / SCP);
    float4 v;
    if (c < DD)       v = *(const float4*)&pts[((long)b*DD + c)*NN + n];
    else if (c < SCn) v = *(const float4*)&xyz[((long)b*3 + (c-DD))*NN + n];
    else              v = make_float4(0.f,0.f,0.f,0.f);
    *(float4*)&d_agg[e] = v;
}

// ---------------- warp-cooperative ball query ----------------
__global__ void k_ballquery() {
    __shared__ float4 sp[NN];
    int b = blockIdx.y;
    for (int j = threadIdx.x; j < NN; j += 256) {
        sp[j] = make_float4(d_xyz_t[(b*NN+j)*3+0], d_xyz_t[(b*NN+j)*3+1],
                            d_xyz_t[(b*NN+j)*3+2], d_xn[b*NN+j]);
    }
    __syncthreads();
    int warp = threadIdx.x >> 5, lane = threadIdx.x & 31;
    int i = blockIdx.x * 8 + warp;
    float4 q = sp[i];
    const float R2 = 0.04f;
    int base = (b*NN + i) * NS;
    int cnt = 0, first = -1;
    for (int j0 = 0; j0 < NN; j0 += 32) {
        float4 p = sp[j0 + lane];
        float sq = q.w + p.w - 2.f*(q.x*p.x + q.y*p.y + q.z*p.z);
        bool hit = !(sq > R2);
        unsigned mask = __ballot_sync(0xffffffffu, hit);
        if (mask) {
            if (first < 0) first = j0 + __ffs(mask) - 1;
            int pos = cnt + __popc(mask & ((1u << lane) - 1));
            if (hit && pos < NS) d_idx[base + pos] = j0 + lane;
            cnt += __popc(mask);
            if (cnt >= NS) break;
        }
    }
    if (cnt < NS && lane >= cnt && lane < NS) d_idx[base + lane] = first;
}

// ---------------- second moment ----------------
__global__ void k_cov() {
    int ci = (blockIdx.x % 5) * 16, cj = (blockIdx.x / 5) * 16;
    int chunk = blockIdx.y;
    int b = chunk >> 3, n0 = (chunk & 7) * 256;
    __shared__ float As[16][260];
    __shared__ float Bs[16][260];
    for (int q = threadIdx.x; q < 1024; q += 256) {
        int r = q >> 6, c4 = (q & 63) * 4;
        *(float4*)&As[r][c4] = *(const float4*)&d_agg[((long)b*SCP + ci + r)*NN + n0 + c4];
        *(float4*)&Bs[r][c4] = *(const float4*)&d_agg[((long)b*SCP + cj + r)*NN + n0 + c4];
    }
    __syncthreads();
    int r = threadIdx.x >> 4, c = threadIdx.x & 15;
    float s = 0.f;
    #pragma unroll 8
    for (int k = 0; k < 256; k++) s += As[r][k] * Bs[c][k];
    atomicAdd(&d_cov[(ci+r)*COVP + cj + c], s);
}

__global__ void k_mu() {
    int c = blockIdx.x;
    float s = 0.f;
    for (int i = threadIdx.x; i < BB*NN; i += 256) {
        int b = i >> 11, n = i & 2047;
        s += d_agg[((long)b*SCP + c)*NN + n];
    }
    __shared__ float r[256];
    r[threadIdx.x] = s; __syncthreads();
    for (int o = 128; o > 0; o >>= 1) { if (threadIdx.x < o) r[threadIdx.x] += r[threadIdx.x+o]; __syncthreads(); }
    if (threadIdx.x == 0) d_mu[c] = r[0];
}

__global__ void k_scale1(const float* __restrict__ w1, const float* __restrict__ g) {
    int m = blockIdx.x;
    __shared__ float sw[SCn];
    if (threadIdx.x < SCn) sw[threadIdx.x] = w1[m*SCn + threadIdx.x];
    __syncthreads();
    float s = 0.f, mu = 0.f;
    for (int p = threadIdx.x; p < SCn*SCn; p += 128) {
        int c = p / SCn, c2 = p % SCn;
        s += sw[c]*sw[c2]*d_cov[c*COVP + c2];
    }
    for (int c = threadIdx.x; c < SCn; c += 128) mu += sw[c]*d_mu[c];
    __shared__ float rs[128], rm[128];
    rs[threadIdx.x] = s; rm[threadIdx.x] = mu; __syncthreads();
    for (int o = 64; o > 0; o >>= 1) {
        if (threadIdx.x < o) { rs[threadIdx.x] += rs[threadIdx.x+o]; rm[threadIdx.x] += rm[threadIdx.x+o]; }
        __syncthreads();
    }
    if (threadIdx.x == 0) {
        const float T = (float)(BB*NN);
        float mh = rm[0] / T;
        float var = rs[0] / T - mh*mh;
        d_scale1[m] = g[m] * rsqrtf(var + 1e-5f);
    }
}

__global__ void k_fold(const float* __restrict__ w2, const float* __restrict__ w1) {
    int o = blockIdx.x;
    __shared__ float sm[SCn];
    int t = threadIdx.x;
    if (t < SCn) sm[t] = w2[o*SCn + t] * d_scale1[t];
    __syncthreads();
    float acc = 0.f;
    if (t < SCn) {
        #pragma unroll 1
        for (int m = 0; m < SCn; m++) acc += sm[m] * w1[m*SCn + t];
    }
    d_w2p[o*SCP + t] = acc;
}

// split conv0 weights: var (edge-varying ch) + inv (k-invariant ch); pre-round all
__global__ void k_padw(const float* __restrict__ c0, const float* __restrict__ c1,
                       const float* __restrict__ c2) {
    int i = blockIdx.x * blockDim.x + threadIdx.x;
    if (i < 128*ECV) {
        int r = i / ECV, c = i % ECV;
        float v = 0.f, w = 0.f;
        if (c < 64)      { v = c0[r*134 + 64 + c];  w = c0[r*134 + c]; }
        else if (c < 67) { v = c0[r*134 + 131 + (c-64)]; w = c0[r*134 + 128 + (c-64)]; }
        d_w0var[i] = (c < 67) ? tfr(v) : 0.f;
        d_w0inv[i] = (c < 67) ? tfr(w) : 0.f;
    }
    if (i < 128*128) d_w1r[i] = tfr(c1[i]);
    if (i < 256*128) d_w2r[i] = tfr(c2[i]);
}

__global__ void k_finalize(const float* __restrict__ stat, float cnt,
                           const float* __restrict__ g, const float* __restrict__ bb,
                           float* __restrict__ scale, float* __restrict__ shift, int C) {
    int c = blockIdx.x*blockDim.x + threadIdx.x;
    if (c >= C) return;
    float m = stat[c*2] / cnt;
    float var = stat[c*2+1] / cnt - m*m;
    float sc = g[c] * rsqrtf(var + 1e-5f);
    scale[c] = sc; shift[c] = bb[c] - m*sc;
}

// ---------------- pipelined tf32 tensor GEMM ----------------
template<int TRANSB, int BAFF, int BLEAKY, int STATS, int MAXMIN, int NOSTORE, int SWAP, int CVT, int ADDC>
__global__ void __launch_bounds__(256, 2) mma_tf32(
        const float* __restrict__ A, const float* __restrict__ B, float* __restrict__ C,
        int K, int lda, int ldb, int ldc, long sA, long sB, long sC,
        const float* __restrict__ bscale, const float* __restrict__ bshift,
        float* __restrict__ stat, const float* __restrict__ yadd)
{
    extern __shared__ float smemf[];
    constexpr int ASZ = 128*36;
    constexpr int BSZ = TRANSB ? 128*36 : 32*136;
    constexpr int STG = ASZ + BSZ;
    int bz = blockIdx.z;
    const float* Ab = A + (long)bz * sA;
    const float* Bb = B + (long)bz * sB;
    float* Cb = C + (long)bz * sC;
    int t = threadIdx.x;
    int lane = t & 31, warp = t >> 5;
    int g = lane >> 2, tg = lane & 3;
    int wm = (warp >> 2) * 64, wn = (warp & 3) * 32;
    long bm = SWAP ? (long)blockIdx.x * 128 : (long)blockIdx.y * 128;
    long bn = SWAP ? (long)blockIdx.y * 128 : (long)blockIdx.x * 128;
    int ar = t >> 3, ac = (t & 7) * 4;
    int br = t >> 5, bc = (t & 31) * 4;
    float acc[4][4][4] = {};

    uint32_t smem_sh = (uint32_t)__cvta_generic_to_shared(smemf);
    int arow = (wm + (lane & 7) + ((lane >> 3) & 1)*8)*36 + (lane >> 4)*4;
    int brow = (lane & 7)*36 + ((lane >> 3) & 1)*4;

    auto issue = [&](int s, int k0) {
        uint32_t sa = smem_sh + (uint32_t)(s*STG)*4;
        #pragma unroll
        for (int p = 0; p < 4; p++) {
            uint32_t dst = sa + ((ar + 32*p)*36 + ac)*4;
            const float* src = &Ab[(bm + ar + 32*p)*(long)lda + k0 + ac];
            asm volatile("cp.async.cg.shared.global [%0], [%1], 16;" :: "r"(dst), "l"(src));
        }
        uint32_t sb = sa + ASZ*4;
        if (TRANSB) {
            #pragma unroll
            for (int p = 0; p < 4; p++) {
                uint32_t dst = sb + ((ar + 32*p)*36 + ac)*4;
                const float* src = &Bb[(bn + ar + 32*p)*(long)ldb + k0 + ac];
                asm volatile("cp.async.cg.shared.global [%0], [%1], 16;" :: "r"(dst), "l"(src));
            }
        } else {
            #pragma unroll
            for (int p = 0; p < 4; p++) {
                uint32_t dst = sb + ((br + 8*p)*136 + bc)*4;
                const float* src = &Bb[(long)(k0 + br + 8*p)*ldb + bn + bc];
                asm volatile("cp.async.cg.shared.global [%0], [%1], 16;" :: "r"(dst), "l"(src));
            }
        }
    };

    int tiles = K >> 5;
    issue(0, 0);
    asm volatile("cp.async.commit_group;");
    issue(1, 32);
    asm volatile("cp.async.commit_group;");
    int k0 = 64;
    int rs = 0;

    for (int kt = 0; kt < tiles; kt++) {
        asm volatile("cp.async.wait_group %0;" :: "n"(1));
        __syncthreads();
        if (k0 < K) {
            int ws = rs + 2; if (ws >= 3) ws -= 3;
            issue(ws, k0);
            k0 += 32;
        }
        asm volatile("cp.async.commit_group;");

        uint32_t saA = smem_sh + (uint32_t)(rs*STG)*4;
        uint32_t saB = saA + ASZ*4;
        float* sBp = smemf + rs*STG + ASZ;
        float scv[8], shv[8];
        if (BAFF) {
            int kb = kt * 32;
            #pragma unroll
            for (int q = 0; q < 8; q++) {
                int kk = kb + (q >> 1)*8 + (q & 1)*4 + tg;
                scv[q] = bscale[kk];
                shv[q] = bshift[kk];
            }
        }
        #pragma unroll
        for (int ks = 0; ks < 32; ks += 8) {
            int sidx = ks >> 3;
            uint32_t a0[4], a1[4], a2[4], a3[4];
            #pragma unroll
            for (int i = 0; i < 4; i++) {
                ldsm4(a0[i], a1[i], a2[i], a3[i], saA + (uint32_t)(arow + i*576 + ks)*4);
                if (CVT) {
                    a0[i] = tf32b(__uint_as_float(a0[i]));
                    a1[i] = tf32b(__uint_as_float(a1[i]));
                    a2[i] = tf32b(__uint_as_float(a2[i]));
                    a3[i] = tf32b(__uint_as_float(a3[i]));
                }
            }
            #pragma unroll
            for (int j = 0; j < 4; j++) {
                uint32_t b0, b1;
                if (TRANSB) {
                    ldsm2(b0, b1, saB + (uint32_t)((wn + j*8)*36 + brow + ks)*4);
                    if (CVT) {
                        b0 = tf32b(__uint_as_float(b0));
                        b1 = tf32b(__uint_as_float(b1));
                    }
                } else {
                    float r0 = sBp[(ks + tg    )*136 + wn + j*8 + g];
                    float r1 = sBp[(ks + tg + 4)*136 + wn + j*8 + g];
                    if (BAFF) {
                        r0 = fmaf(scv[2*sidx], r0, shv[2*sidx]);
                        r1 = fmaf(scv[2*sidx+1], r1, shv[2*sidx+1]);
                        if (BLEAKY) {
                            r0 = r0 > 0.f ? r0 : 0.2f*r0;
                            r1 = r1 > 0.f ? r1 : 0.2f*r1;
                        }
                        b0 = tf32b(r0); b1 = tf32b(r1);
                    } else if (CVT) {
                        b0 = tf32b(r0); b1 = tf32b(r1);
                    } else {
                        b0 = __float_as_uint(r0); b1 = __float_as_uint(r1);
                    }
                }
                #pragma unroll
                for (int i = 0; i < 4; i++) {
                    asm volatile(
                        "mma.sync.aligned.m16n8k8.row.col.f32.tf32.tf32.f32 "
                        "{%0,%1,%2,%3},{%4,%5,%6,%7},{%8,%9},{%0,%1,%2,%3};"
                        : "+f"(acc[i][j][0]), "+f"(acc[i][j][1]),
                          "+f"(acc[i][j][2]), "+f"(acc[i][j][3])
                        : "r"(a0[i]), "r"(a1[i]), "r"(a2[i]), "r"(a3[i]),
                          "r"(b0), "r"(b1));
                }
            }
        }
        rs++; if (rs >= 3) rs = 0;
    }

    if (ADDC) {
        const float* ya = yadd + (long)bz*128*NP;
        #pragma unroll
        for (int i = 0; i < 4; i++) {
            long r0 = bm + wm + i*16 + g;
            #pragma unroll
            for (int j = 0; j < 4; j++) {
                int sg = (int)(bn + wn + j*8 + 2*tg) >> 5;
                float v0 = ya[r0*NP + sg];
                float v8 = ya[(r0 + 8)*NP + sg];
                acc[i][j][0] += v0; acc[i][j][1] += v0;
                acc[i][j][2] += v8; acc[i][j][3] += v8;
            }
        }
    }

    if (!NOSTORE) {
        #pragma unroll
        for (int i = 0; i < 4; i++) {
            long r0 = bm + wm + i*16 + g;
            #pragma unroll
            for (int j = 0; j < 4; j++) {
                long cc = bn + wn + j*8 + 2*tg;
                *(float2*)&Cb[r0 * ldc + cc]       = make_float2(acc[i][j][0], acc[i][j][1]);
                *(float2*)&Cb[(r0 + 8) * ldc + cc] = make_float2(acc[i][j][2], acc[i][j][3]);
            }
        }
    }

    if (MAXMIN) {
        int sg = (int)(bn + wn) >> 5;
        #pragma unroll
        for (int i = 0; i < 4; i++) {
            float mx0 = -1e30f, mn0 = 1e30f, mx8 = -1e30f, mn8 = 1e30f;
            #pragma unroll
            for (int j = 0; j < 4; j++) {
                mx0 = fmaxf(mx0, fmaxf(acc[i][j][0], acc[i][j][1]));
                mn0 = fminf(mn0, fminf(acc[i][j][0], acc[i][j][1]));
                mx8 = fmaxf(mx8, fmaxf(acc[i][j][2], acc[i][j][3]));
                mn8 = fminf(mn8, fminf(acc[i][j][2], acc[i][j][3]));
            }
            mx0 = fmaxf(mx0, __shfl_xor_sync(0xffffffffu, mx0, 1));
            mx0 = fmaxf(mx0, __shfl_xor_sync(0xffffffffu, mx0, 2));
            mn0 = fminf(mn0, __shfl_xor_sync(0xffffffffu, mn0, 1));
            mn0 = fminf(mn0, __shfl_xor_sync(0xffffffffu, mn0, 2));
            mx8 = fmaxf(mx8, __shfl_xor_sync(0xffffffffu, mx8, 1));
            mx8 = fmaxf(mx8, __shfl_xor_sync(0xffffffffu, mx8, 2));
            mn8 = fminf(mn8, __shfl_xor_sync(0xffffffffu, mn8, 1));
            mn8 = fminf(mn8, __shfl_xor_sync(0xffffffffu, mn8, 2));
            if (tg == 0) {
                long r0 = bm + wm + i*16 + g;
                d_ymax[((long)bz*256 + r0)*NP + sg]     = mx0;
                d_ymin[((long)bz*256 + r0)*NP + sg]     = mn0;
                d_ymax[((long)bz*256 + r0 + 8)*NP + sg] = mx8;
                d_ymin[((long)bz*256 + r0 + 8)*NP + sg] = mn8;
            }
        }
    }

    if (STATS) {
        asm volatile("cp.async.wait_group %0;" :: "n"(0));
        __syncthreads();
        if (t < 256) smemf[t] = 0.f;
        __syncthreads();
        #pragma unroll
        for (int i = 0; i < 4; i++) {
            float s0 = 0.f, q0 = 0.f, s8 = 0.f, q8 = 0.f;
            #pragma unroll
            for (int j = 0; j < 4; j++) {
                s0 += acc[i][j][0] + acc[i][j][1];
                q0 += acc[i][j][0]*acc[i][j][0] + acc[i][j][1]*acc[i][j][1];
                s8 += acc[i][j][2] + acc[i][j][3];
                q8 += acc[i][j][2]*acc[i][j][2] + acc[i][j][3]*acc[i][j][3];
            }
            s0 += __shfl_xor_sync(0xffffffffu, s0, 1); s0 += __shfl_xor_sync(0xffffffffu, s0, 2);
            q0 += __shfl_xor_sync(0xffffffffu, q0, 1); q0 += __shfl_xor_sync(0xffffffffu, q0, 2);
            s8 += __shfl_xor_sync(0xffffffffu, s8, 1); s8 += __shfl_xor_sync(0xffffffffu, s8, 2);
            q8 += __shfl_xor_sync(0xffffffffu, q8, 1); q8 += __shfl_xor_sync(0xffffffffu, q8, 2);
            if (tg == 0) {
                int r = wm + i*16 + g;
                atomicAdd(&smemf[r*2],       s0);
                atomicAdd(&smemf[r*2+1],     q0);
                atomicAdd(&smemf[(r+8)*2],   s8);
                atomicAdd(&smemf[(r+8)*2+1], q8);
            }
        }
        __syncthreads();
        if (t < 256)
            atomicAdd(&stat[(bm + (t >> 1))*2 + (t & 1)], smemf[t]);
    }
}

// ---------------- softmax ----------------
__global__ void k_softmax() {
    int b = blockIdx.x >> 9;
    int s = blockIdx.x & 511;
    float* row = d_h2 + ((long)(b*NP + s)) * NN;
    float sc = d_scale2[s], sh = d_shift2[s];
    int base = threadIdx.x * 8;
    float4 u0 = *(const float4*)&row[base];
    float4 u1 = *(const float4*)&row[base+4];
    float v[8] = { fmaf(sc,u0.x,sh), fmaf(sc,u0.y,sh), fmaf(sc,u0.z,sh), fmaf(sc,u0.w,sh),
                   fmaf(sc,u1.x,sh), fmaf(sc,u1.y,sh), fmaf(sc,u1.z,sh), fmaf(sc,u1.w,sh) };
    float mymax = -1e30f; int myarg = 0;
    #pragma unroll
    for (int q = 0; q < 8; q++)
        if (v[q] > mymax) { mymax = v[q]; myarg = base + q; }
    __shared__ float rv[256];
    __shared__ int ri[256];
    __shared__ float rq[256];
    rv[threadIdx.x] = mymax; ri[threadIdx.x] = myarg; __syncthreads();
    for (int o = 128; o > 0; o >>= 1) {
        if (threadIdx.x < o) {
            float v2 = rv[threadIdx.x+o]; int i2 = ri[threadIdx.x+o];
            if (v2 > rv[threadIdx.x] || (v2 == rv[threadIdx.x] && i2 < ri[threadIdx.x])) {
                rv[threadIdx.x] = v2; ri[threadIdx.x] = i2;
            }
        }
        __syncthreads();
    }
    float M = rv[0]; int amax = ri[0];
    __syncthreads();
    float S = 0.f;
    #pragma unroll
    for (int q = 0; q < 8; q++) {
        float e = expf(v[q] - M);
        v[q] = e;
        S += e;
    }
    rv[threadIdx.x] = S; __syncthreads();
    for (int o = 128; o > 0; o >>= 1) {
        if (threadIdx.x < o) rv[threadIdx.x] += rv[threadIdx.x+o];
        __syncthreads();
    }
    S = rv[0];
    float inv = 1.f / S;
    float Q = 0.f;
    #pragma unroll
    for (int q = 0; q < 8; q++) {
        float r = tfr(v[q] * inv);
        v[q] = r;
        Q += r*r;
    }
    rq[threadIdx.x] = Q; __syncthreads();
    for (int o = 128; o > 0; o >>= 1) {
        if (threadIdx.x < o) rq[threadIdx.x] += rq[threadIdx.x+o];
        __syncthreads();
    }
    Q = rq[0];
    u0 = make_float4(v[0], v[1], v[2], v[3]);
    u1 = make_float4(v[4], v[5], v[6], v[7]);
    *(float4*)&row[base]   = u0;
    *(float4*)&row[base+4] = u1;
    if (threadIdx.x == 0) {
        d_norm[b*NP + s] = sqrtf(Q);
        if (b == 0) d_amax[s] = amax;
    }
}

// ---------------- unique ----------------
__global__ void k_unique() {
    __shared__ unsigned char fl[NN];
    for (int i = threadIdx.x; i < NN; i += 256) fl[i] = 0;
    __syncthreads();
    for (int s = threadIdx.x; s < NP; s += 256) fl[d_amax[s]] = 1;
    __syncthreads();
    __shared__ int r[256];
    int c = 0;
    for (int i = threadIdx.x; i < NN; i += 256) c += fl[i];
    r[threadIdx.x] = c; __syncthreads();
    for (int o = 128; o > 0; o >>= 1) { if (threadIdx.x < o) r[threadIdx.x] += r[threadIdx.x+o]; __syncthreads(); }
    if (threadIdx.x == 0) d_unique = r[0];
}

// ---------------- cos loss ----------------
__global__ void k_cos() {
    int b = blockIdx.x;
    const float* in = d_inner + (long)b*NP*NP;
    const float* nr = d_norm + b*NP;
    float acc = 0.f;
    for (int i = threadIdx.x; i < NP*NP; i += 256) {
        int s = i >> 9, tt = i & 511;
        if (s != tt) {
            float c = in[i] / (nr[s]*nr[tt] + 1e-10f);
            acc += c*c;
        }
    }
    __shared__ float r[256];
    r[threadIdx.x] = acc; __syncthreads();
    for (int o = 128; o > 0; o >>= 1) { if (threadIdx.x < o) r[threadIdx.x] += r[threadIdx.x+o]; __syncthreads(); }
    if (threadIdx.x == 0) d_bsum[b] = sqrtf(r[0]);
}

// ---------------- gather RHS (tf32-prerounded) ----------------
__global__ void k_bmat() {
    int n = blockIdx.x, b = blockIdx.y;
    __shared__ int sj[NS];
    if (threadIdx.x < NS) sj[threadIdx.x] = d_idx[(b*NN+n)*NS + threadIdx.x];
    __syncthreads();
    float* dst = d_bmat + ((long)(b*NN + n))*GCOLSP;
    for (int q = threadIdx.x; q < 561; q += 128) {
        float4 v;
        if (q < 16) {
            v = *(const float4*)&d_pts[(((long)b*NN + n) << 6) + q*4];
        } else if (q < 528) {
            int rel = q*4 - 64; int k = rel >> 6, d = rel & 63;
            v = *(const float4*)&d_pts[(((long)b*NN + sj[k]) << 6) + d];
        } else if (q == 528) {
            const float* xp = &d_xyz_t[(b*NN + n)*3];
            v = make_float4(xp[0], xp[1], xp[2], 0.f);
        } else {
            int k = q - 529;
            const float* xp = &d_xyz_t[(b*NN + sj[k])*3];
            v = make_float4(xp[0], xp[1], xp[2], 0.f);
        }
        v.x = tfr(v.x); v.y = tfr(v.y); v.z = tfr(v.z); v.w = tfr(v.w);
        *(float4*)&dst[q*4] = v;
    }
}

// ---------------- new_xyz ----------------
__global__ void k_newxyz(float* __restrict__ out) {
    int i = blockIdx.x*blockDim.x + threadIdx.x;
    if (i >= BB*3*NP) return;
    int b = i / (3*NP); int r = i % (3*NP); int c = r / NP; int s = r % NP;
    out[i] = d_sg[((long)(b*NP + s))*GCOLSP + XYZCOL + c];
}

// ---------------- spmat: k-invariant channels [sp(64) | cx(3) | 0] ---------
__global__ void k_spmat() {
    int r = blockIdx.x, b = blockIdx.y;
    int s = threadIdx.x;   // 512 threads
    float v = 0.f;
    if (r < 64)      v = d_sg[((long)(b*NP + s))*GCOLSP + r];
    else if (r < 67) v = d_sg[((long)(b*NP + s))*GCOLSP + XYZCOL + (r - 64)];
    d_spmat[((long)b*ECV + r)*NP + s] = tfr(v);
}

// ---------------- edge tensor: varying channels only ----------------
__global__ void k_edge() {
    int s = blockIdx.x, b = blockIdx.y;
    __shared__ float srow[2340];
    const float* rp = d_sg + ((long)(b*NP + s))*GCOLSP;
    for (int q = threadIdx.x; q < 561; q += 256) {
        float4 v = *(const float4*)&rp[q*4];
        int col = q*4; int si = col + (col >> 6);
        srow[si] = v.x; srow[si+1] = v.y; srow[si+2] = v.z; srow[si+3] = v.w;
    }
    __syncthreads();
    int k = threadIdx.x & 31, c0 = threadIdx.x >> 5;
    long obase = ((long)b*ECV)*CONV_N + s*32 + k;
    #define SS(x) srow[(x) + ((x) >> 6)]
    for (int c = c0; c < 67; c += 8) {
        float v;
        if (c < 64) v = SS(DD + k*DD + c) - SS(c);
        else        { int cc = c - 64; v = SS(GXCOL + k*4 + cc) - SS(XYZCOL + cc); }
        d_edge[obase + (long)c*CONV_N] = tfr(v);
    }
    #undef SS
}

// ---------------- maxpool from per-(o,s) max/min ----------------
__global__ void k_maxpool(float* __restrict__ out) {
    int i = blockIdx.x*blockDim.x + threadIdx.x;
    if (i >= BB*256*NP) return;
    int o = (i / NP) % 256;
    float sc = d_scaleC2[o], sh = d_shiftC2[o];
    float v = (sc >= 0.f) ? d_ymax[i] : d_ymin[i];
    float r = fmaf(sc, v, sh);
    r = r > 0.f ? r : 0.2f*r;
    out[24576 + i] = r;
}

// ---------------- scalars ----------------
__global__ void k_final(float* __restrict__ out) {
    if (threadIdx.x == 0 && blockIdx.x == 0) {
        float s = 0.f;
        for (int b = 0; b < BB; b++) s += d_bsum[b];
        out[2121728] = s / (float)BB;
        out[2121729] = (float)d_unique;
    }
}

// ---------------- host ----------------
template <typename T>
static T* symaddr(const void* sym) { void* p = nullptr; cudaGetSymbolAddress(&p, sym); return (T*)p; }

#define SMEM_NN   (3*(128*36 + 32*136)*4)
#define SMEM_NT   (3*(128*36 + 128*36)*4)

extern "C" void kernel_launch(void* const* d_in, const int* in_sizes, int n_in,
                              void* d_out, int out_size) {
    const float* xyz    = (const float*)d_in[0];
    const float* points = (const float*)d_in[1];
    const float* w1_w   = (const float*)d_in[2];
    const float* bn1_g  = (const float*)d_in[4];
    const float* w2_w   = (const float*)d_in[6];
    const float* bn2_g  = (const float*)d_in[8];
    const float* bn2_b  = (const float*)d_in[9];
    const float* c0_w   = (const float*)d_in[10];
    const float* bng0   = (const float*)d_in[12];
    const float* bnb0   = (const float*)d_in[13];
    const float* c1_w   = (const float*)d_in[14];
    const float* bng1   = (const float*)d_in[16];
    const float* bnb1   = (const float*)d_in[17];
    const float* c2_w   = (const float*)d_in[18];
    const float* bng2   = (const float*)d_in[20];
    const float* bnb2   = (const float*)d_in[21];
    float* out = (float*)d_out;

    float* p_agg  = symaddr<float>(d_agg);
    float* p_h2   = symaddr<float>(d_h2);
    float* p_in   = symaddr<float>(d_inner);
    float* p_bm   = symaddr<float>(d_bmat);
    float* p_sg   = symaddr<float>(d_sg);
    float* p_e    = symaddr<float>(d_edge);
    float* p_sp   = symaddr<float>(d_spmat);
    float* p_yi   = symaddr<float>(d_yinv);
    float* p_y1   = symaddr<float>(d_y1);
    float* p_y2   = symaddr<float>(d_y2);
    float* p_sc2  = symaddr<float>(d_scale2);
    float* p_sh2  = symaddr<float>(d_shift2);
    float* p_sC0  = symaddr<float>(d_scaleC0);
    float* p_hC0  = symaddr<float>(d_shiftC0);
    float* p_sC1  = symaddr<float>(d_scaleC1);
    float* p_hC1  = symaddr<float>(d_shiftC1);
    float* p_sC2  = symaddr<float>(d_scaleC2);
    float* p_hC2  = symaddr<float>(d_shiftC2);
    float* p_w2p  = symaddr<float>(d_w2p);
    float* p_w0v  = symaddr<float>(d_w0var);
    float* p_w0i  = symaddr<float>(d_w0inv);
    float* p_w1r  = symaddr<float>(d_w1r);
    float* p_w2r  = symaddr<float>(d_w2r);
    float* p_st   = symaddr<float>(d_stats);

    static int attr_done = 0;
    if (!attr_done) {
        cudaFuncSetAttribute(mma_tf32<1,0,0,0,0,0,0,0,0>, cudaFuncAttributeMaxDynamicSharedMemorySize, SMEM_NT);
        cudaFuncSetAttribute(mma_tf32<0,0,0,0,0,0,1,0,0>, cudaFuncAttributeMaxDynamicSharedMemorySize, SMEM_NN);
        cudaFuncSetAttribute(mma_tf32<0,0,0,1,0,0,0,1,0>, cudaFuncAttributeMaxDynamicSharedMemorySize, SMEM_NN);
        cudaFuncSetAttribute(mma_tf32<0,0,0,0,0,0,0,0,0>, cudaFuncAttributeMaxDynamicSharedMemorySize, SMEM_NN);
        cudaFuncSetAttribute(mma_tf32<0,0,0,1,0,0,0,0,1>, cudaFuncAttributeMaxDynamicSharedMemorySize, SMEM_NN);
        cudaFuncSetAttribute(mma_tf32<0,1,1,1,0,0,0,0,0>, cudaFuncAttributeMaxDynamicSharedMemorySize, SMEM_NN);
        cudaFuncSetAttribute(mma_tf32<0,1,1,1,1,1,1,0,0>, cudaFuncAttributeMaxDynamicSharedMemorySize, SMEM_NN);
        attr_done = 1;
    }

    k_prepxyz<<<(BB*NN + 255)/256, 256>>>(xyz);
    k_transp<<<dim3(NN/32, DD/32, BB), dim3(32, 8)>>>(points);
    k_agg<<<(unsigned)(((long)BB*SCP*NN/4 + 255)/256), 256>>>(xyz, points);
    k_ballquery<<<dim3(NN/8, BB), 256>>>();
    k_padw<<<(256*128 + 255)/256, 256>>>(c0_w, c1_w, c2_w);

    k_cov<<<dim3(25, 128), 256>>>();
    k_mu<<<SCn, 256>>>();
    k_scale1<<<SCn, 128>>>(w1_w, bn1_g);
    k_fold<<<NP, SCP>>>(w2_w, w1_w);

    // logits: CVT=1
    mma_tf32<0,0,0,1,0,0,0,1,0><<<dim3(16, 4, BB), 256, SMEM_NN>>>(
        p_w2p, p_agg, p_h2, SCP, SCP, NN, NN, 0L, (long)SCP*NN, (long)NP*NN,
        nullptr, nullptr, p_st + OFF_L, nullptr);
    k_finalize<<<1, 512>>>(p_st + OFF_L, (float)(BB*NN), bn2_g, bn2_b, p_sc2, p_sh2, NP);
    k_softmax<<<BB*NP, 256>>>();
    k_unique<<<1, 256>>>();

    // inner (NT, ldsm both)
    mma_tf32<1,0,0,0,0,0,0,0,0><<<dim3(4, 4, BB), 256, SMEM_NT>>>(
        p_h2, p_h2, p_in, NN, NN, NN, NP, (long)NP*NN, (long)NP*NN, (long)NP*NP,
        nullptr, nullptr, nullptr, nullptr);
    k_cos<<<BB, 256>>>();

    k_bmat<<<dim3(NN, BB), 128>>>();
    mma_tf32<0,0,0,0,0,0,1,0,0><<<dim3(4, 18, BB), 256, SMEM_NN>>>(
        p_h2, p_bm, p_sg, NN, NN, GCOLSP, GCOLSP, (long)NP*NN, (long)NN*GCOLSP, (long)NP*GCOLSP,
        nullptr, nullptr, nullptr, nullptr);
    k_newxyz<<<(BB*3*NP + 255)/256, 256>>>(out);

    k_spmat<<<dim3(ECV, BB), 512>>>();
    k_edge<<<dim3(NP, BB), 256>>>();

    // yinv = w0inv @ spmat (tiny GEMM, 128x512xK96 per batch)
    mma_tf32<0,0,0,0,0,0,0,0,0><<<dim3(4, 1, BB), 256, SMEM_NN>>>(
        p_w0i, p_sp, p_yi, ECV, ECV, NP, NP, 0L, (long)ECV*NP, (long)128*NP,
        nullptr, nullptr, nullptr, nullptr);

    // conv0 var part + yinv add + stats
    mma_tf32<0,0,0,1,0,0,0,0,1><<<dim3(128, 1, BB), 256, SMEM_NN>>>(
        p_w0v, p_e, p_y1, ECV, ECV, CONV_N, CONV_N, 0L, (long)ECV*CONV_N, (long)128*CONV_N,
        nullptr, nullptr, p_st + OFF_0, p_yi);
    k_finalize<<<1, 128>>>(p_st + OFF_0, (float)(BB*CONV_N), bng0, bnb0, p_sC0, p_hC0, 128);

    mma_tf32<0,1,1,1,0,0,0,0,0><<<dim3(128, 1, BB), 256, SMEM_NN>>>(
        p_w1r, p_y1, p_y2, 128, 128, CONV_N, CONV_N, 0L, (long)128*CONV_N, (long)128*CONV_N,
        p_sC0, p_hC0, p_st + OFF_1, nullptr);
    k_finalize<<<1, 128>>>(p_st + OFF_1, (float)(BB*CONV_N), bng1, bnb1, p_sC1, p_hC1, 128);

    mma_tf32<0,1,1,1,1,1,1,0,0><<<dim3(2, 128, BB), 256, SMEM_NN>>>(
        p_w2r, p_y2, p_y1, 128, 128, CONV_N, CONV_N, 0L, (long)128*CONV_N, 0L,
        p_sC1, p_hC1, p_st + OFF_2, nullptr);
    k_finalize<<<1, 256>>>(p_st + OFF_2, (float)(BB*CONV_N), bng2, bnb2, p_sC2, p_hC2, 256);

    k_maxpool<<<(BB*256*NP + 255)/256, 256>>>(out);
    k_final<<<1, 32>>>(out);
    (void)in_sizes; (void)n_in; (void)out_size;
}

// round 15
// speedup vs baseline: 1.0067x; 1.0067x over previous
#include <cuda_runtime.h>
#include <cstdint>

#define BB 16
#define NN 2048
#define DD 64
#define SCn 67
#define SCP 96
#define COVP 80
#define NP 512
#define NS 32
#define GCOLSP 2304
#define XYZCOL 2112
#define GXCOL 2116
#define EC 134
#define ECP 160
#define CONV_N 16384

#define OFF_L 0
#define OFF_0 1024
#define OFF_1 1280
#define OFF_2 1536

__device__ float d_xyz_t[BB*NN*3];
__device__ float d_xn[BB*NN];
__device__ float d_pts[BB*NN*DD];
__device__ int   d_idx[BB*NN*NS];
__device__ float d_agg[(long)BB*SCP*NN];
__device__ float d_h2[BB*NP*NN];
__device__ float d_norm[BB*NP];
__device__ int   d_amax[NP];
__device__ float d_scale1[SCn];
__device__ float d_scale2[NP],  d_shift2[NP];
__device__ float d_scaleC0[128], d_shiftC0[128];
__device__ float d_scaleC1[128], d_shiftC1[128];
__device__ float d_scaleC2[256], d_shiftC2[256];
__device__ float d_inner[BB*NP*NP];
__device__ float d_bmat[(long)BB*NN*GCOLSP];
__device__ float d_sg[BB*NP*GCOLSP];
__device__ float d_edge[(long)BB*ECP*CONV_N];
__device__ float d_y1[(long)BB*128*CONV_N];
__device__ float d_y2[(long)BB*128*CONV_N];
__device__ float d_ymax[(long)BB*256*NP];
__device__ float d_ymin[(long)BB*256*NP];
__device__ float d_w2p[NP*SCP];
__device__ float d_w0p[128*ECP];
__device__ float d_w1r[128*128];
__device__ float d_w2r[256*128];
__device__ float d_cov[COVP*COVP];
__device__ float d_mu[COVP];
__device__ float d_stats[2048];
__device__ float d_bsum[BB];
__device__ int   d_unique;

__device__ __forceinline__ uint32_t tf32b(float x) {
    uint32_t u; asm("cvt.rna.tf32.f32 %0, %1;" : "=r"(u) : "f"(x)); return u;
}
__device__ __forceinline__ float tfr(float x) { return __uint_as_float(tf32b(x)); }

__device__ __forceinline__ void ldsm4(uint32_t& r0, uint32_t& r1, uint32_t& r2, uint32_t& r3, uint32_t addr) {
    asm volatile("ldmatrix.sync.aligned.m8n8.x4.shared.b16 {%0,%1,%2,%3}, [%4];"
        : "=r"(r0), "=r"(r1), "=r"(r2), "=r"(r3) : "r"(addr));
}
__device__ __forceinline__ void ldsm2(uint32_t& r0, uint32_t& r1, uint32_t addr) {
    asm volatile("ldmatrix.sync.aligned.m8n8.x2.shared.b16 {%0,%1}, [%2];"
        : "=r"(r0), "=r"(r1) : "r"(addr));
}

// ---------------- prep: xyz transpose + norms + zero accumulators ----------
__global__ void k_prepxyz(const float* __restrict__ xyz) {
    int i = blockIdx.x * blockDim.x + threadIdx.x;
    if (i < 2048) d_stats[i] = 0.f;
    if (i < COVP*COVP) d_cov[i] = 0.f;
    if (i < COVP) d_mu[i] = 0.f;
    if (i >= BB*NN) return;
    int b = i / NN, n = i % NN;
    float x = xyz[(b*3+0)*NN + n];
    float y = xyz[(b*3+1)*NN + n];
    float z = xyz[(b*3+2)*NN + n];
    d_xyz_t[i*3+0] = x; d_xyz_t[i*3+1] = y; d_xyz_t[i*3+2] = z;
    d_xn[i] = x*x + y*y + z*z;
}

// ---------------- pts tiled transpose ----------------
__global__ void k_transp(const float* __restrict__ pts) {
    __shared__ float tile[32][33];
    int n0 = blockIdx.x * 32, c0 = blockIdx.y * 32, b = blockIdx.z;
    int tx = threadIdx.x, ty = threadIdx.y;
    #pragma unroll
    for (int r = 0; r < 4; r++)
        tile[ty + 8*r][tx] = pts[((long)b*DD + c0 + ty + 8*r)*NN + n0 + tx];
    __syncthreads();
    #pragma unroll
    for (int r = 0; r < 4; r++)
        d_pts[((long)b*NN + n0 + ty + 8*r)*DD + c0 + tx] = tile[tx][ty + 8*r];
}

// ---------------- agg ----------------
__global__ void k_agg(const float* __restrict__ xyz, const float* __restrict__ pts) {
    long i = (long)blockIdx.x*blockDim.x + threadIdx.x;
    long tot4 = (long)BB*SCP*NN/4;
    if (i >= tot4) return;
    long e = i*4;
    int n = (int)(e % NN); long bc = e / NN; int c = (int)(bc % SCP); int b = (int)(bc / SCP);
    float4 v;
    if (c < DD)       v = *(const float4*)&pts[((long)b*DD + c)*NN + n];
    else if (c < SCn) v = *(const float4*)&xyz[((long)b*3 + (c-DD))*NN + n];
    else              v = make_float4(0.f,0.f,0.f,0.f);
    *(float4*)&d_agg[e] = v;
}

// ---------------- warp-cooperative ball query (32 queries per smem fill) ----
__global__ void __launch_bounds__(1024, 2) k_ballquery() {
    __shared__ float4 sp[NN];
    int b = blockIdx.y;
    for (int j = threadIdx.x; j < NN; j += 1024) {
        sp[j] = make_float4(d_xyz_t[(b*NN+j)*3+0], d_xyz_t[(b*NN+j)*3+1],
                            d_xyz_t[(b*NN+j)*3+2], d_xn[b*NN+j]);
    }
    __syncthreads();
    int warp = threadIdx.x >> 5, lane = threadIdx.x & 31;
    int i = blockIdx.x * 32 + warp;
    float4 q = sp[i];
    const float R2 = 0.04f;
    int base = (b*NN + i) * NS;
    int cnt = 0, first = -1;
    for (int j0 = 0; j0 < NN; j0 += 32) {
        float4 p = sp[j0 + lane];
        float sq = q.w + p.w - 2.f*(q.x*p.x + q.y*p.y + q.z*p.z);
        bool hit = !(sq > R2);
        unsigned mask = __ballot_sync(0xffffffffu, hit);
        if (mask) {
            if (first < 0) first = j0 + __ffs(mask) - 1;
            int pos = cnt + __popc(mask & ((1u << lane) - 1));
            if (hit && pos < NS) d_idx[base + pos] = j0 + lane;
            cnt += __popc(mask);
            if (cnt >= NS) break;
        }
    }
    if (cnt < NS && lane >= cnt && lane < NS) d_idx[base + lane] = first;
}

// ---------------- second moment ----------------
__global__ void k_cov() {
    int ci = (blockIdx.x % 5) * 16, cj = (blockIdx.x / 5) * 16;
    int chunk = blockIdx.y;
    int b = chunk >> 3, n0 = (chunk & 7) * 256;
    __shared__ float As[16][260];
    __shared__ float Bs[16][260];
    for (int q = threadIdx.x; q < 1024; q += 256) {
        int r = q >> 6, c4 = (q & 63) * 4;
        *(float4*)&As[r][c4] = *(const float4*)&d_agg[((long)b*SCP + ci + r)*NN + n0 + c4];
        *(float4*)&Bs[r][c4] = *(const float4*)&d_agg[((long)b*SCP + cj + r)*NN + n0 + c4];
    }
    __syncthreads();
    int r = threadIdx.x >> 4, c = threadIdx.x & 15;
    float s = 0.f;
    #pragma unroll 8
    for (int k = 0; k < 256; k++) s += As[r][k] * Bs[c][k];
    atomicAdd(&d_cov[(ci+r)*COVP + cj + c], s);
}

__global__ void k_mu() {
    int c = blockIdx.x;
    float s = 0.f;
    for (int i = threadIdx.x; i < BB*NN; i += 256) {
        int b = i >> 11, n = i & 2047;
        s += d_agg[((long)b*SCP + c)*NN + n];
    }
    __shared__ float r[256];
    r[threadIdx.x] = s; __syncthreads();
    for (int o = 128; o > 0; o >>= 1) { if (threadIdx.x < o) r[threadIdx.x] += r[threadIdx.x+o]; __syncthreads(); }
    if (threadIdx.x == 0) d_mu[c] = r[0];
}

__global__ void k_scale1(const float* __restrict__ w1, const float* __restrict__ g) {
    int m = blockIdx.x;
    __shared__ float sw[SCn];
    if (threadIdx.x < SCn) sw[threadIdx.x] = w1[m*SCn + threadIdx.x];
    __syncthreads();
    float s = 0.f, mu = 0.f;
    for (int p = threadIdx.x; p < SCn*SCn; p += 128) {
        int c = p / SCn, c2 = p % SCn;
        s += sw[c]*sw[c2]*d_cov[c*COVP + c2];
    }
    for (int c = threadIdx.x; c < SCn; c += 128) mu += sw[c]*d_mu[c];
    __shared__ float rs[128], rm[128];
    rs[threadIdx.x] = s; rm[threadIdx.x] = mu; __syncthreads();
    for (int o = 64; o > 0; o >>= 1) {
        if (threadIdx.x < o) { rs[threadIdx.x] += rs[threadIdx.x+o]; rm[threadIdx.x] += rm[threadIdx.x+o]; }
        __syncthreads();
    }
    if (threadIdx.x == 0) {
        const float T = (float)(BB*NN);
        float mh = rm[0] / T;
        float var = rs[0] / T - mh*mh;
        d_scale1[m] = g[m] * rsqrtf(var + 1e-5f);
    }
}

__global__ void k_fold(const float* __restrict__ w2, const float* __restrict__ w1) {
    int o = blockIdx.x;
    __shared__ float sm[SCn];
    int t = threadIdx.x;
    if (t < SCn) sm[t] = w2[o*SCn + t] * d_scale1[t];
    __syncthreads();
    float acc = 0.f;
    if (t < SCn) {
        #pragma unroll 1
        for (int m = 0; m < SCn; m++) acc += sm[m] * w1[m*SCn + t];
    }
    d_w2p[o*SCP + t] = acc;
}

__global__ void k_padw(const float* __restrict__ c0, const float* __restrict__ c1,
                       const float* __restrict__ c2) {
    int i = blockIdx.x * blockDim.x + threadIdx.x;
    if (i < 128*ECP) {
        int r = i / ECP, c = i % ECP;
        d_w0p[i] = (c < EC) ? tfr(c0[r*EC + c]) : 0.f;
    }
    if (i < 128*128) d_w1r[i] = tfr(c1[i]);
    if (i < 256*128) d_w2r[i] = tfr(c2[i]);
}

__global__ void k_finalize(const float* __restrict__ stat, float cnt,
                           const float* __restrict__ g, const float* __restrict__ bb,
                           float* __restrict__ scale, float* __restrict__ shift, int C) {
    int c = blockIdx.x*blockDim.x + threadIdx.x;
    if (c >= C) return;
    float m = stat[c*2] / cnt;
    float var = stat[c*2+1] / cnt - m*m;
    float sc = g[c] * rsqrtf(var + 1e-5f);
    scale[c] = sc; shift[c] = bb[c] - m*sc;
}

// ---------------- pipelined tf32 tensor GEMM (LDSM fragment loads) ----------
template<int TRANSB, int BAFF, int BLEAKY, int STATS, int MAXMIN, int NOSTORE, int SWAP, int CVT>
__global__ void __launch_bounds__(256, 2) mma_tf32(
        const float* __restrict__ A, const float* __restrict__ B, float* __restrict__ C,
        int K, int lda, int ldb, int ldc, long sA, long sB, long sC,
        const float* __restrict__ bscale, const float* __restrict__ bshift,
        float* __restrict__ stat)
{
    extern __shared__ float smemf[];
    constexpr int ASZ = 128*36;
    constexpr int BSZ = TRANSB ? 128*36 : 32*136;
    constexpr int STG = ASZ + BSZ;
    int bz = blockIdx.z;
    const float* Ab = A + (long)bz * sA;
    const float* Bb = B + (long)bz * sB;
    float* Cb = C + (long)bz * sC;
    int t = threadIdx.x;
    int lane = t & 31, warp = t >> 5;
    int g = lane >> 2, tg = lane & 3;
    int wm = (warp >> 2) * 64, wn = (warp & 3) * 32;
    long bm = SWAP ? (long)blockIdx.x * 128 : (long)blockIdx.y * 128;
    long bn = SWAP ? (long)blockIdx.y * 128 : (long)blockIdx.x * 128;
    int ar = t >> 3, ac = (t & 7) * 4;
    int br = t >> 5, bc = (t & 31) * 4;
    float acc[4][4][4] = {};

    uint32_t smem_sh = (uint32_t)__cvta_generic_to_shared(smemf);
    int arow = (wm + (lane & 7) + ((lane >> 3) & 1)*8)*36 + (lane >> 4)*4;
    int brow = (lane & 7)*36 + ((lane >> 3) & 1)*4;

    auto issue = [&](int s, int k0) {
        uint32_t sa = smem_sh + (uint32_t)(s*STG)*4;
        #pragma unroll
        for (int p = 0; p < 4; p++) {
            uint32_t dst = sa + ((ar + 32*p)*36 + ac)*4;
            const float* src = &Ab[(bm + ar + 32*p)*(long)lda + k0 + ac];
            asm volatile("cp.async.cg.shared.global [%0], [%1], 16;" :: "r"(dst), "l"(src));
        }
        uint32_t sb = sa + ASZ*4;
        if (TRANSB) {
            #pragma unroll
            for (int p = 0; p < 4; p++) {
                uint32_t dst = sb + ((ar + 32*p)*36 + ac)*4;
                const float* src = &Bb[(bn + ar + 32*p)*(long)ldb + k0 + ac];
                asm volatile("cp.async.cg.shared.global [%0], [%1], 16;" :: "r"(dst), "l"(src));
            }
        } else {
            #pragma unroll
            for (int p = 0; p < 4; p++) {
                uint32_t dst = sb + ((br + 8*p)*136 + bc)*4;
                const float* src = &Bb[(long)(k0 + br + 8*p)*ldb + bn + bc];
                asm volatile("cp.async.cg.shared.global [%0], [%1], 16;" :: "r"(dst), "l"(src));
            }
        }
    };

    int tiles = K >> 5;
    issue(0, 0);
    asm volatile("cp.async.commit_group;");
    issue(1, 32);
    asm volatile("cp.async.commit_group;");
    int k0 = 64;
    int rs = 0;

    for (int kt = 0; kt < tiles; kt++) {
        asm volatile("cp.async.wait_group %0;" :: "n"(1));
        __syncthreads();
        if (k0 < K) {
            int ws = rs + 2; if (ws >= 3) ws -= 3;
            issue(ws, k0);
            k0 += 32;
        }
        asm volatile("cp.async.commit_group;");

        uint32_t saA = smem_sh + (uint32_t)(rs*STG)*4;
        uint32_t saB = saA + ASZ*4;
        float* sBp = smemf + rs*STG + ASZ;
        float scv[8], shv[8];
        if (BAFF) {
            int kb = kt * 32;
            #pragma unroll
            for (int q = 0; q < 8; q++) {
                int kk = kb + (q >> 1)*8 + (q & 1)*4 + tg;
                scv[q] = bscale[kk];
                shv[q] = bshift[kk];
            }
        }
        #pragma unroll
        for (int ks = 0; ks < 32; ks += 8) {
            int sidx = ks >> 3;
            uint32_t a0[4], a1[4], a2[4], a3[4];
            #pragma unroll
            for (int i = 0; i < 4; i++) {
                ldsm4(a0[i], a1[i], a2[i], a3[i], saA + (uint32_t)(arow + i*576 + ks)*4);
                if (CVT) {
                    a0[i] = tf32b(__uint_as_float(a0[i]));
                    a1[i] = tf32b(__uint_as_float(a1[i]));
                    a2[i] = tf32b(__uint_as_float(a2[i]));
                    a3[i] = tf32b(__uint_as_float(a3[i]));
                }
            }
            #pragma unroll
            for (int j = 0; j < 4; j++) {
                uint32_t b0, b1;
                if (TRANSB) {
                    ldsm2(b0, b1, saB + (uint32_t)((wn + j*8)*36 + brow + ks)*4);
                    if (CVT) {
                        b0 = tf32b(__uint_as_float(b0));
                        b1 = tf32b(__uint_as_float(b1));
                    }
                } else {
                    float r0 = sBp[(ks + tg    )*136 + wn + j*8 + g];
                    float r1 = sBp[(ks + tg + 4)*136 + wn + j*8 + g];
                    if (BAFF) {
                        r0 = fmaf(scv[2*sidx], r0, shv[2*sidx]);
                        r1 = fmaf(scv[2*sidx+1], r1, shv[2*sidx+1]);
                        if (BLEAKY) {
                            r0 = r0 > 0.f ? r0 : 0.2f*r0;
                            r1 = r1 > 0.f ? r1 : 0.2f*r1;
                        }
                        b0 = tf32b(r0); b1 = tf32b(r1);
                    } else if (CVT) {
                        b0 = tf32b(r0); b1 = tf32b(r1);
                    } else {
                        b0 = __float_as_uint(r0); b1 = __float_as_uint(r1);
                    }
                }
                #pragma unroll
                for (int i = 0; i < 4; i++) {
                    asm volatile(
                        "mma.sync.aligned.m16n8k8.row.col.f32.tf32.tf32.f32 "
                        "{%0,%1,%2,%3},{%4,%5,%6,%7},{%8,%9},{%0,%1,%2,%3};"
                        : "+f"(acc[i][j][0]), "+f"(acc[i][j][1]),
                          "+f"(acc[i][j][2]), "+f"(acc[i][j][3])
                        : "r"(a0[i]), "r"(a1[i]), "r"(a2[i]), "r"(a3[i]),
                          "r"(b0), "r"(b1));
                }
            }
        }
        rs++; if (rs >= 3) rs = 0;
    }

    if (!NOSTORE) {
        #pragma unroll
        for (int i = 0; i < 4; i++) {
            long r0 = bm + wm + i*16 + g;
            #pragma unroll
            for (int j = 0; j < 4; j++) {
                long cc = bn + wn + j*8 + 2*tg;
                *(float2*)&Cb[r0 * ldc + cc]       = make_float2(acc[i][j][0], acc[i][j][1]);
                *(float2*)&Cb[(r0 + 8) * ldc + cc] = make_float2(acc[i][j][2], acc[i][j][3]);
            }
        }
    }

    if (MAXMIN) {
        int sg = (int)(bn + wn) >> 5;
        #pragma unroll
        for (int i = 0; i < 4; i++) {
            float mx0 = -1e30f, mn0 = 1e30f, mx8 = -1e30f, mn8 = 1e30f;
            #pragma unroll
            for (int j = 0; j < 4; j++) {
                mx0 = fmaxf(mx0, fmaxf(acc[i][j][0], acc[i][j][1]));
                mn0 = fminf(mn0, fminf(acc[i][j][0], acc[i][j][1]));
                mx8 = fmaxf(mx8, fmaxf(acc[i][j][2], acc[i][j][3]));
                mn8 = fminf(mn8, fminf(acc[i][j][2], acc[i][j][3]));
            }
            mx0 = fmaxf(mx0, __shfl_xor_sync(0xffffffffu, mx0, 1));
            mx0 = fmaxf(mx0, __shfl_xor_sync(0xffffffffu, mx0, 2));
            mn0 = fminf(mn0, __shfl_xor_sync(0xffffffffu, mn0, 1));
            mn0 = fminf(mn0, __shfl_xor_sync(0xffffffffu, mn0, 2));
            mx8 = fmaxf(mx8, __shfl_xor_sync(0xffffffffu, mx8, 1));
            mx8 = fmaxf(mx8, __shfl_xor_sync(0xffffffffu, mx8, 2));
            mn8 = fminf(mn8, __shfl_xor_sync(0xffffffffu, mn8, 1));
            mn8 = fminf(mn8, __shfl_xor_sync(0xffffffffu, mn8, 2));
            if (tg == 0) {
                long r0 = bm + wm + i*16 + g;
                d_ymax[((long)bz*256 + r0)*NP + sg]     = mx0;
                d_ymin[((long)bz*256 + r0)*NP + sg]     = mn0;
                d_ymax[((long)bz*256 + r0 + 8)*NP + sg] = mx8;
                d_ymin[((long)bz*256 + r0 + 8)*NP + sg] = mn8;
            }
        }
    }

    if (STATS) {
        asm volatile("cp.async.wait_group %0;" :: "n"(0));
        __syncthreads();
        if (t < 256) smemf[t] = 0.f;
        __syncthreads();
        #pragma unroll
        for (int i = 0; i < 4; i++) {
            float s0 = 0.f, q0 = 0.f, s8 = 0.f, q8 = 0.f;
            #pragma unroll
            for (int j = 0; j < 4; j++) {
                s0 += acc[i][j][0] + acc[i][j][1];
                q0 += acc[i][j][0]*acc[i][j][0] + acc[i][j][1]*acc[i][j][1];
                s8 += acc[i][j][2] + acc[i][j][3];
                q8 += acc[i][j][2]*acc[i][j][2] + acc[i][j][3]*acc[i][j][3];
            }
            s0 += __shfl_xor_sync(0xffffffffu, s0, 1); s0 += __shfl_xor_sync(0xffffffffu, s0, 2);
            q0 += __shfl_xor_sync(0xffffffffu, q0, 1); q0 += __shfl_xor_sync(0xffffffffu, q0, 2);
            s8 += __shfl_xor_sync(0xffffffffu, s8, 1); s8 += __shfl_xor_sync(0xffffffffu, s8, 2);
            q8 += __shfl_xor_sync(0xffffffffu, q8, 1); q8 += __shfl_xor_sync(0xffffffffu, q8, 2);
            if (tg == 0) {
                int r = wm + i*16 + g;
                atomicAdd(&smemf[r*2],       s0);
                atomicAdd(&smemf[r*2+1],     q0);
                atomicAdd(&smemf[(r+8)*2],   s8);
                atomicAdd(&smemf[(r+8)*2+1], q8);
            }
        }
        __syncthreads();
        if (t < 256)
            atomicAdd(&stat[(bm + (t >> 1))*2 + (t & 1)], smemf[t]);
    }
}

// ---------------- softmax ----------------
__global__ void k_softmax() {
    int b = blockIdx.x >> 9;
    int s = blockIdx.x & 511;
    float* row = d_h2 + ((long)(b*NP + s)) * NN;
    float sc = d_scale2[s], sh = d_shift2[s];
    int base = threadIdx.x * 8;
    float4 u0 = *(const float4*)&row[base];
    float4 u1 = *(const float4*)&row[base+4];
    float v[8] = { fmaf(sc,u0.x,sh), fmaf(sc,u0.y,sh), fmaf(sc,u0.z,sh), fmaf(sc,u0.w,sh),
                   fmaf(sc,u1.x,sh), fmaf(sc,u1.y,sh), fmaf(sc,u1.z,sh), fmaf(sc,u1.w,sh) };
    float mymax = -1e30f; int myarg = 0;
    #pragma unroll
    for (int q = 0; q < 8; q++)
        if (v[q] > mymax) { mymax = v[q]; myarg = base + q; }
    __shared__ float rv[256];
    __shared__ int ri[256];
    __shared__ float rq[256];
    rv[threadIdx.x] = mymax; ri[threadIdx.x] = myarg; __syncthreads();
    for (int o = 128; o > 0; o >>= 1) {
        if (threadIdx.x < o) {
            float v2 = rv[threadIdx.x+o]; int i2 = ri[threadIdx.x+o];
            if (v2 > rv[threadIdx.x] || (v2 == rv[threadIdx.x] && i2 < ri[threadIdx.x])) {
                rv[threadIdx.x] = v2; ri[threadIdx.x] = i2;
            }
        }
        __syncthreads();
    }
    float M = rv[0]; int amax = ri[0];
    __syncthreads();
    float S = 0.f;
    #pragma unroll
    for (int q = 0; q < 8; q++) {
        float e = expf(v[q] - M);
        v[q] = e;
        S += e;
    }
    rv[threadIdx.x] = S; __syncthreads();
    for (int o = 128; o > 0; o >>= 1) {
        if (threadIdx.x < o) rv[threadIdx.x] += rv[threadIdx.x+o];
        __syncthreads();
    }
    S = rv[0];
    float inv = 1.f / S;
    float Q = 0.f;
    #pragma unroll
    for (int q = 0; q < 8; q++) {
        float r = tfr(v[q] * inv);
        v[q] = r;
        Q += r*r;
    }
    rq[threadIdx.x] = Q; __syncthreads();
    for (int o = 128; o > 0; o >>= 1) {
        if (threadIdx.x < o) rq[threadIdx.x] += rq[threadIdx.x+o];
        __syncthreads();
    }
    Q = rq[0];
    u0 = make_float4(v[0], v[1], v[2], v[3]);
    u1 = make_float4(v[4], v[5], v[6], v[7]);
    *(float4*)&row[base]   = u0;
    *(float4*)&row[base+4] = u1;
    if (threadIdx.x == 0) {
        d_norm[b*NP + s] = sqrtf(Q);
        if (b == 0) d_amax[s] = amax;
    }
}

// ---------------- unique ----------------
__global__ void k_unique() {
    __shared__ unsigned char fl[NN];
    for (int i = threadIdx.x; i < NN; i += 256) fl[i] = 0;
    __syncthreads();
    for (int s = threadIdx.x; s < NP; s += 256) fl[d_amax[s]] = 1;
    __syncthreads();
    __shared__ int r[256];
    int c = 0;
    for (int i = threadIdx.x; i < NN; i += 256) c += fl[i];
    r[threadIdx.x] = c; __syncthreads();
    for (int o = 128; o > 0; o >>= 1) { if (threadIdx.x < o) r[threadIdx.x] += r[threadIdx.x+o]; __syncthreads(); }
    if (threadIdx.x == 0) d_unique = r[0];
}

// ---------------- cos loss ----------------
__global__ void k_cos() {
    int b = blockIdx.x;
    const float* in = d_inner + (long)b*NP*NP;
    const float* nr = d_norm + b*NP;
    float acc = 0.f;
    for (int i = threadIdx.x; i < NP*NP; i += 256) {
        int s = i >> 9, tt = i & 511;
        if (s != tt) {
            float c = in[i] / (nr[s]*nr[tt] + 1e-10f);
            acc += c*c;
        }
    }
    __shared__ float r[256];
    r[threadIdx.x] = acc; __syncthreads();
    for (int o = 128; o > 0; o >>= 1) { if (threadIdx.x < o) r[threadIdx.x] += r[threadIdx.x+o]; __syncthreads(); }
    if (threadIdx.x == 0) d_bsum[b] = sqrtf(r[0]);
}

// ---------------- gather RHS (tf32-prerounded) ----------------
__global__ void k_bmat() {
    int n = blockIdx.x, b = blockIdx.y;
    __shared__ int sj[NS];
    if (threadIdx.x < NS) sj[threadIdx.x] = d_idx[(b*NN+n)*NS + threadIdx.x];
    __syncthreads();
    float* dst = d_bmat + ((long)(b*NN + n))*GCOLSP;
    for (int q = threadIdx.x; q < 561; q += 128) {
        float4 v;
        if (q < 16) {
            v = *(const float4*)&d_pts[(((long)b*NN + n) << 6) + q*4];
        } else if (q < 528) {
            int rel = q*4 - 64; int k = rel >> 6, d = rel & 63;
            v = *(const float4*)&d_pts[(((long)b*NN + sj[k]) << 6) + d];
        } else if (q == 528) {
            const float* xp = &d_xyz_t[(b*NN + n)*3];
            v = make_float4(xp[0], xp[1], xp[2], 0.f);
        } else {
            int k = q - 529;
            const float* xp = &d_xyz_t[(b*NN + sj[k])*3];
            v = make_float4(xp[0], xp[1], xp[2], 0.f);
        }
        v.x = tfr(v.x); v.y = tfr(v.y); v.z = tfr(v.z); v.w = tfr(v.w);
        *(float4*)&dst[q*4] = v;
    }
}

// ---------------- new_xyz ----------------
__global__ void k_newxyz(float* __restrict__ out) {
    int i = blockIdx.x*blockDim.x + threadIdx.x;
    if (i >= BB*3*NP) return;
    int b = i / (3*NP); int r = i % (3*NP); int c = r / NP; int s = r % NP;
    out[i] = d_sg[((long)(b*NP + s))*GCOLSP + XYZCOL + c];
}

// ---------------- edge tensor (tf32-prerounded) ----------------
__global__ void k_edge() {
    int s = blockIdx.x, b = blockIdx.y;
    __shared__ float srow[2340];
    const float* rp = d_sg + ((long)(b*NP + s))*GCOLSP;
    for (int q = threadIdx.x; q < 561; q += 256) {
        float4 v = *(const float4*)&rp[q*4];
        int col = q*4; int si = col + (col >> 6);
        srow[si] = v.x; srow[si+1] = v.y; srow[si+2] = v.z; srow[si+3] = v.w;
    }
    __syncthreads();
    int k = threadIdx.x & 31, c0 = threadIdx.x >> 5;
    long obase = ((long)b*ECP)*CONV_N + s*32 + k;
    #define SS(x) srow[(x) + ((x) >> 6)]
    for (int c = c0; c < EC; c += 8) {
        float v;
        if (c < DD)            v = SS(c);
        else if (c < 2*DD)     { int d = c - DD; v = SS(DD + k*DD + d) - SS(d); }
        else if (c < 2*DD + 3) v = SS(XYZCOL + (c - 2*DD));
        else                   { int cc = c - (2*DD + 3); v = SS(GXCOL + k*4 + cc) - SS(XYZCOL + cc); }
        d_edge[obase + (long)c*CONV_N] = tfr(v);
    }
    #undef SS
}

// ---------------- maxpool from per-(o,s) max/min ----------------
__global__ void k_maxpool(float* __restrict__ out) {
    int i = blockIdx.x*blockDim.x + threadIdx.x;
    if (i >= BB*256*NP) return;
    int o = (i / NP) % 256;
    float sc = d_scaleC2[o], sh = d_shiftC2[o];
    float v = (sc >= 0.f) ? d_ymax[i] : d_ymin[i];
    float r = fmaf(sc, v, sh);
    r = r > 0.f ? r : 0.2f*r;
    out[24576 + i] = r;
}

// ---------------- scalars ----------------
__global__ void k_final(float* __restrict__ out) {
    if (threadIdx.x == 0 && blockIdx.x == 0) {
        float s = 0.f;
        for (int b = 0; b < BB; b++) s += d_bsum[b];
        out[2121728] = s / (float)BB;
        out[2121729] = (float)d_unique;
    }
}

// ---------------- host ----------------
template <typename T>
static T* symaddr(const void* sym) { void* p = nullptr; cudaGetSymbolAddress(&p, sym); return (T*)p; }

#define SMEM_NN   (3*(128*36 + 32*136)*4)
#define SMEM_NT   (3*(128*36 + 128*36)*4)

extern "C" void kernel_launch(void* const* d_in, const int* in_sizes, int n_in,
                              void* d_out, int out_size) {
    const float* xyz    = (const float*)d_in[0];
    const float* points = (const float*)d_in[1];
    const float* w1_w   = (const float*)d_in[2];
    const float* bn1_g  = (const float*)d_in[4];
    const float* w2_w   = (const float*)d_in[6];
    const float* bn2_g  = (const float*)d_in[8];
    const float* bn2_b  = (const float*)d_in[9];
    const float* c0_w   = (const float*)d_in[10];
    const float* bng0   = (const float*)d_in[12];
    const float* bnb0   = (const float*)d_in[13];
    const float* c1_w   = (const float*)d_in[14];
    const float* bng1   = (const float*)d_in[16];
    const float* bnb1   = (const float*)d_in[17];
    const float* c2_w   = (const float*)d_in[18];
    const float* bng2   = (const float*)d_in[20];
    const float* bnb2   = (const float*)d_in[21];
    float* out = (float*)d_out;

    float* p_agg  = symaddr<float>(d_agg);
    float* p_h2   = symaddr<float>(d_h2);
    float* p_in   = symaddr<float>(d_inner);
    float* p_bm   = symaddr<float>(d_bmat);
    float* p_sg   = symaddr<float>(d_sg);
    float* p_e    = symaddr<float>(d_edge);
    float* p_y1   = symaddr<float>(d_y1);
    float* p_y2   = symaddr<float>(d_y2);
    float* p_sc2  = symaddr<float>(d_scale2);
    float* p_sh2  = symaddr<float>(d_shift2);
    float* p_sC0  = symaddr<float>(d_scaleC0);
    float* p_hC0  = symaddr<float>(d_shiftC0);
    float* p_sC1  = symaddr<float>(d_scaleC1);
    float* p_hC1  = symaddr<float>(d_shiftC1);
    float* p_sC2  = symaddr<float>(d_scaleC2);
    float* p_hC2  = symaddr<float>(d_shiftC2);
    float* p_w2p  = symaddr<float>(d_w2p);
    float* p_w0p  = symaddr<float>(d_w0p);
    float* p_w1r  = symaddr<float>(d_w1r);
    float* p_w2r  = symaddr<float>(d_w2r);
    float* p_st   = symaddr<float>(d_stats);

    static int attr_done = 0;
    if (!attr_done) {
        cudaFuncSetAttribute(mma_tf32<1,0,0,0,0,0,0,0>, cudaFuncAttributeMaxDynamicSharedMemorySize, SMEM_NT);
        cudaFuncSetAttribute(mma_tf32<0,0,0,0,0,0,1,0>, cudaFuncAttributeMaxDynamicSharedMemorySize, SMEM_NN);
        cudaFuncSetAttribute(mma_tf32<0,0,0,1,0,0,0,1>, cudaFuncAttributeMaxDynamicSharedMemorySize, SMEM_NN);
        cudaFuncSetAttribute(mma_tf32<0,0,0,1,0,0,0,0>, cudaFuncAttributeMaxDynamicSharedMemorySize, SMEM_NN);
        cudaFuncSetAttribute(mma_tf32<0,1,1,1,0,0,0,0>, cudaFuncAttributeMaxDynamicSharedMemorySize, SMEM_NN);
        cudaFuncSetAttribute(mma_tf32<0,1,1,1,1,1,1,0>, cudaFuncAttributeMaxDynamicSharedMemorySize, SMEM_NN);
        attr_done = 1;
    }

    k_prepxyz<<<(BB*NN + 255)/256, 256>>>(xyz);
    k_transp<<<dim3(NN/32, DD/32, BB), dim3(32, 8)>>>(points);
    k_agg<<<(unsigned)(((long)BB*SCP*NN/4 + 255)/256), 256>>>(xyz, points);
    k_ballquery<<<dim3(NN/32, BB), 1024>>>();
    k_padw<<<(256*128 + 255)/256, 256>>>(c0_w, c1_w, c2_w);

    k_cov<<<dim3(25, 128), 256>>>();
    k_mu<<<SCn, 256>>>();
    k_scale1<<<SCn, 128>>>(w1_w, bn1_g);
    k_fold<<<NP, SCP>>>(w2_w, w1_w);

    // logits: CVT=1 (operands unrounded)
    mma_tf32<0,0,0,1,0,0,0,1><<<dim3(16, 4, BB), 256, SMEM_NN>>>(
        p_w2p, p_agg, p_h2, SCP, SCP, NN, NN, 0L, (long)SCP*NN, (long)NP*NN,
        nullptr, nullptr, p_st + OFF_L);
    k_finalize<<<1, 512>>>(p_st + OFF_L, (float)(BB*NN), bn2_g, bn2_b, p_sc2, p_sh2, NP);
    k_softmax<<<BB*NP, 256>>>();
    k_unique<<<1, 256>>>();

    // inner: select pre-rounded -> CVT=0 (A ldsm + B ldsm)
    mma_tf32<1,0,0,0,0,0,0,0><<<dim3(4, 4, BB), 256, SMEM_NT>>>(
        p_h2, p_h2, p_in, NN, NN, NN, NP, (long)NP*NN, (long)NP*NN, (long)NP*NP,
        nullptr, nullptr, nullptr);
    k_cos<<<BB, 256>>>();

    k_bmat<<<dim3(NN, BB), 128>>>();
    // sg: both pre-rounded -> CVT=0
    mma_tf32<0,0,0,0,0,0,1,0><<<dim3(4, 18, BB), 256, SMEM_NN>>>(
        p_h2, p_bm, p_sg, NN, NN, GCOLSP, GCOLSP, (long)NP*NN, (long)NN*GCOLSP, (long)NP*GCOLSP,
        nullptr, nullptr, nullptr);
    k_newxyz<<<(BB*3*NP + 255)/256, 256>>>(out);

    k_edge<<<dim3(NP, BB), 256>>>();

    // conv0: pre-rounded -> CVT=0
    mma_tf32<0,0,0,1,0,0,0,0><<<dim3(128, 1, BB), 256, SMEM_NN>>>(
        p_w0p, p_e, p_y1, ECP, ECP, CONV_N, CONV_N, 0L, (long)ECP*CONV_N, (long)128*CONV_N,
        nullptr, nullptr, p_st + OFF_0);
    k_finalize<<<1, 128>>>(p_st + OFF_0, (float)(BB*CONV_N), bng0, bnb0, p_sC0, p_hC0, 128);

    // conv1: A pre-rounded; B affined in-loop
    mma_tf32<0,1,1,1,0,0,0,0><<<dim3(128, 1, BB), 256, SMEM_NN>>>(
        p_w1r, p_y1, p_y2, 128, 128, CONV_N, CONV_N, 0L, (long)128*CONV_N, (long)128*CONV_N,
        p_sC0, p_hC0, p_st + OFF_1);
    k_finalize<<<1, 128>>>(p_st + OFF_1, (float)(BB*CONV_N), bng1, bnb1, p_sC1, p_hC1, 128);

    // conv2: A pre-rounded; max/min epilogue, no y3 store
    mma_tf32<0,1,1,1,1,1,1,0><<<dim3(2, 128, BB), 256, SMEM_NN>>>(
        p_w2r, p_y2, p_y1, 128, 128, CONV_N, CONV_N, 0L, (long)128*CONV_N, 0L,
        p_sC1, p_hC1, p_st + OFF_2);
    k_finalize<<<1, 256>>>(p_st + OFF_2, (float)(BB*CONV_N), bng2, bnb2, p_sC2, p_hC2, 256);

    k_maxpool<<<(BB*256*NP + 255)/256, 256>>>(out);
    k_final<<<1, 32>>>(out);
    (void)in_sizes; (void)n_in; (void)out_size;
}